// round 12
// baseline (speedup 1.0000x reference)
#include <cuda_runtime.h>
#include <cuda_bf16.h>
#include <cuda_fp8.h>
#include <cstdint>
#include <cstddef>

// ============================================================================
// Problem constants
// ============================================================================
#define DIM 4096
#define NELEM ((size_t)DIM * (size_t)DIM)

// GEMM tiling (R5 config: proven best)
#define BM 128
#define BN 128
#define BK 64                        // 64 bf16 = 128 bytes per smem row
#define NKITER (DIM / BK)            // 64
#define STAGES 3
#define TILE_BYTES (BM * BK * 2)     // 16 KB per operand tile
#define STAGE_BYTES (2 * TILE_BYTES) // 32 KB (A + B)
#define SMEM_TOTAL (STAGES * STAGE_BYTES)  // 96 KB -> 2 CTAs / SM
#define BK_BYTES (BK * 2)
#define NTILES ((DIM / BM) * (DIM / BN))   // 1024; 32 tiles per M-row (row-major)

// ============================================================================
// Scratch (device globals — no allocations allowed)
// ============================================================================
__device__ __align__(1024) __nv_bfloat16 g_X  [NELEM];  // quantized x       [M,K] K-major
__device__ __align__(1024) __nv_bfloat16 g_W1T[NELEM];  // quantized mat1^T  [N,K] K-major
__device__ __align__(1024) __nv_bfloat16 g_W2T[NELEM];  // quantized mat2^T  [N,K] K-major
__device__ __align__(1024) __nv_bfloat16 g_H2 [NELEM];  // requantized GEMM1 out [M,K] K-major

// Sync state (memset to 0 before the fused kernel each call):
// [0] = phase-1 dynamic tile counter, [1] = phase-2 counter,
// [2..33] = completed GEMM1 tiles per 128-row stripe.
__device__ int g_sync[34];

// ============================================================================
// Helpers
// ============================================================================
__device__ __forceinline__ uint32_t smem_u32(const void* p) {
    uint32_t a;
    asm("{ .reg .u64 t; cvta.to.shared.u64 t, %1; cvt.u32.u64 %0, t; }" : "=r"(a) : "l"(p));
    return a;
}

__device__ __forceinline__ void ldmatrix_x4(uint32_t* r, uint32_t addr) {
    asm volatile("ldmatrix.sync.aligned.m8n8.x4.shared.b16 {%0,%1,%2,%3}, [%4];"
                 : "=r"(r[0]), "=r"(r[1]), "=r"(r[2]), "=r"(r[3]) : "r"(addr));
}

__device__ __forceinline__ void mma_16816(float* c, const uint32_t* a, uint32_t b0, uint32_t b1) {
    asm volatile(
        "mma.sync.aligned.m16n8k16.row.col.f32.bf16.bf16.f32 "
        "{%0,%1,%2,%3}, {%4,%5,%6,%7}, {%8,%9}, {%0,%1,%2,%3};"
        : "+f"(c[0]), "+f"(c[1]), "+f"(c[2]), "+f"(c[3])
        : "r"(a[0]), "r"(a[1]), "r"(a[2]), "r"(a[3]), "r"(b0), "r"(b1));
}

// ============================================================================
// MX quant-dequant (exact match of the reference semantics)
// ============================================================================
__device__ __forceinline__ float mx_qd(float v, float amax) {
    if (amax == 0.0f) return 0.0f;              // all-zero block
    int e;
    frexpf(amax, &e);                           // amax = m * 2^e, m in [0.5,1)
    int se = (e - 1) - 8;                       // floor(log2(amax)) - 8 (exact)
    se = max(-127, min(127, se));
    float vs = ldexpf(v, -se);                  // v / 2^se, exact
    __nv_fp8_storage_t q = __nv_cvt_float_to_fp8(vs, __NV_SATFINITE, __NV_E4M3);
    __half_raw hr = __nv_cvt_fp8_to_halfraw(q, __NV_E4M3);
    return ldexpf(__half2float(*reinterpret_cast<__half*>(&hr)), se);
}

// ============================================================================
// Vectorized quantize along contiguous dim: 8 lanes x float4 = one 32-block.
// ============================================================================
__global__ void quant_rows_v4(const float4* __restrict__ in, uint2* __restrict__ out) {
    size_t idx = (size_t)blockIdx.x * blockDim.x + threadIdx.x;
    float4 v = in[idx];
    float a = fmaxf(fmaxf(fabsf(v.x), fabsf(v.y)), fmaxf(fabsf(v.z), fabsf(v.w)));
    #pragma unroll
    for (int off = 4; off >= 1; off >>= 1)
        a = fmaxf(a, __shfl_xor_sync(0xFFFFFFFFu, a, off, 8));
    __nv_bfloat16 q0 = __float2bfloat16(mx_qd(v.x, a));
    __nv_bfloat16 q1 = __float2bfloat16(mx_qd(v.y, a));
    __nv_bfloat16 q2 = __float2bfloat16(mx_qd(v.z, a));
    __nv_bfloat16 q3 = __float2bfloat16(mx_qd(v.w, a));
    uint2 o;
    o.x = ((uint32_t)__bfloat16_as_ushort(q1) << 16) | __bfloat16_as_ushort(q0);
    o.y = ((uint32_t)__bfloat16_as_ushort(q3) << 16) | __bfloat16_as_ushort(q2);
    out[idx] = o;
}

// Quantize mat[R, C] along last dim (C, blocks of 32), write transposed [C, R] bf16.
__global__ void quant_transpose_v4(const float* __restrict__ in, __nv_bfloat16* __restrict__ out) {
    __shared__ __nv_bfloat16 tile[32][36];   // [c][r], padded
    const int tid = threadIdx.x;
    const int r0 = blockIdx.y * 32, c0 = blockIdx.x * 32;
    {
        const int r = tid >> 3, cg = tid & 7;
        float4 v = *reinterpret_cast<const float4*>(in + (size_t)(r0 + r) * DIM + c0 + cg * 4);
        float a = fmaxf(fmaxf(fabsf(v.x), fabsf(v.y)), fmaxf(fabsf(v.z), fabsf(v.w)));
        #pragma unroll
        for (int off = 4; off >= 1; off >>= 1)
            a = fmaxf(a, __shfl_xor_sync(0xFFFFFFFFu, a, off, 8));
        tile[cg * 4 + 0][r] = __float2bfloat16(mx_qd(v.x, a));
        tile[cg * 4 + 1][r] = __float2bfloat16(mx_qd(v.y, a));
        tile[cg * 4 + 2][r] = __float2bfloat16(mx_qd(v.z, a));
        tile[cg * 4 + 3][r] = __float2bfloat16(mx_qd(v.w, a));
    }
    __syncthreads();
    {
        const int c = tid >> 3, rg = tid & 7;
        uint2 o = *reinterpret_cast<const uint2*>(&tile[c][rg * 4]);
        *reinterpret_cast<uint2*>(out + (size_t)(c0 + c) * DIM + r0 + rg * 4) = o;
    }
}

// ============================================================================
// One 128x128x4096 output tile (R5 inner machinery, verbatim).
// cp.async.cg only (L2-coherent; required for phase-2 reads of H2).
// ============================================================================
__device__ __forceinline__ void issue_stage(uint32_t sbase, uint32_t slot,
                                            const char* Ag, const char* Bg, uint32_t k0byte,
                                            const uint32_t* rowbyte, const uint32_t* soff) {
    const uint32_t sA = sbase + slot * STAGE_BYTES;
    const uint32_t sB = sA + TILE_BYTES;
    #pragma unroll
    for (int i = 0; i < 4; i++) {
        asm volatile("cp.async.cg.shared.global [%0], [%1], 16;"
                     :: "r"(sA + soff[i]), "l"(Ag + rowbyte[i] + k0byte));
        asm volatile("cp.async.cg.shared.global [%0], [%1], 16;"
                     :: "r"(sB + soff[i]), "l"(Bg + rowbyte[i] + k0byte));
    }
    asm volatile("cp.async.commit_group;" ::: "memory");
}

template <bool REQUANT>
__device__ __forceinline__ void run_tile(
    const __nv_bfloat16* __restrict__ A, const __nv_bfloat16* __restrict__ B,
    void* __restrict__ Cout, int m0, int n0, uint32_t sbase, int lane, int wm, int wn,
    const uint32_t* rowbyte, const uint32_t* soff,
    const uint32_t* aRowOff, const uint32_t* bRowOff,
    const uint32_t* acol, const uint32_t* bcol)
{
    const char* Ag = (const char*)A + (size_t)m0 * (DIM * 2);
    const char* Bg = (const char*)B + (size_t)n0 * (DIM * 2);

    float acc[4][4][4];
    #pragma unroll
    for (int mi = 0; mi < 4; mi++)
        #pragma unroll
        for (int ni = 0; ni < 4; ni++)
            #pragma unroll
            for (int j = 0; j < 4; j++) acc[mi][ni][j] = 0.0f;

    // prologue: fill 2 of 3 stages (caller guarantees a barrier since last reads)
    issue_stage(sbase, 0, Ag, Bg, 0, rowbyte, soff);
    issue_stage(sbase, 1, Ag, Bg, BK_BYTES, rowbyte, soff);
    int slotC = 0, slotP = 2;
    uint32_t kbyte_next = 2 * BK_BYTES;

    for (int kt = 0; kt < NKITER; kt++) {
        asm volatile("cp.async.wait_group 1;" ::: "memory");  // tile kt resident
        __syncthreads();

        if (kt + 2 < NKITER) {
            issue_stage(sbase, (uint32_t)slotP, Ag, Bg, kbyte_next, rowbyte, soff);
            kbyte_next += BK_BYTES;
        } else {
            asm volatile("cp.async.commit_group;" ::: "memory");  // keep group count
        }

        const uint32_t sA = sbase + (uint32_t)slotC * STAGE_BYTES;
        const uint32_t sB = sA + TILE_BYTES;

        #pragma unroll
        for (int ks = 0; ks < BK / 16; ks++) {
            uint32_t afr[4][4], bfr[2][4];
            #pragma unroll
            for (int mi = 0; mi < 4; mi++) ldmatrix_x4(afr[mi], sA + aRowOff[mi] + acol[ks]);
            #pragma unroll
            for (int nj = 0; nj < 2; nj++) ldmatrix_x4(bfr[nj], sB + bRowOff[nj] + bcol[ks]);
            #pragma unroll
            for (int mi = 0; mi < 4; mi++)
                #pragma unroll
                for (int ni = 0; ni < 4; ni++)
                    mma_16816(acc[mi][ni], afr[mi],
                              bfr[ni >> 1][(ni & 1) * 2], bfr[ni >> 1][(ni & 1) * 2 + 1]);
        }

        slotC = (slotC == STAGES - 1) ? 0 : slotC + 1;
        slotP = (slotP == STAGES - 1) ? 0 : slotP + 1;
    }

    // epilogue (register-only sources)
    const int tr = lane >> 2, tc = (lane & 3) * 2;
    if (!REQUANT) {
        float* C = (float*)Cout;
        #pragma unroll
        for (int mi = 0; mi < 4; mi++) {
            const int m = m0 + wm + mi * 16 + tr;
            #pragma unroll
            for (int ni = 0; ni < 4; ni++) {
                const int n = n0 + wn + ni * 8 + tc;
                *reinterpret_cast<float2*>(C + (size_t)m * DIM + n) =
                    make_float2(acc[mi][ni][0], acc[mi][ni][1]);
                *reinterpret_cast<float2*>(C + (size_t)(m + 8) * DIM + n) =
                    make_float2(acc[mi][ni][2], acc[mi][ni][3]);
            }
        }
    } else {
        // Warp's N-range [n0+wn, n0+wn+32) is exactly one MX block per row.
        __nv_bfloat16* C = (__nv_bfloat16*)Cout;
        #pragma unroll
        for (int mi = 0; mi < 4; mi++) {
            #pragma unroll
            for (int h = 0; h < 2; h++) {          // row tr  /  row tr+8
                float a = 0.0f;
                #pragma unroll
                for (int ni = 0; ni < 4; ni++)
                    a = fmaxf(a, fmaxf(fabsf(acc[mi][ni][2 * h]),
                                       fabsf(acc[mi][ni][2 * h + 1])));
                a = fmaxf(a, __shfl_xor_sync(0xFFFFFFFFu, a, 1, 4));
                a = fmaxf(a, __shfl_xor_sync(0xFFFFFFFFu, a, 2, 4));
                const int m = m0 + wm + mi * 16 + h * 8 + tr;
                #pragma unroll
                for (int ni = 0; ni < 4; ni++) {
                    const int n = n0 + wn + ni * 8 + tc;
                    __nv_bfloat16 q0 = __float2bfloat16(mx_qd(acc[mi][ni][2 * h], a));
                    __nv_bfloat16 q1 = __float2bfloat16(mx_qd(acc[mi][ni][2 * h + 1], a));
                    uint32_t pk = ((uint32_t)__bfloat16_as_ushort(q1) << 16) |
                                  __bfloat16_as_ushort(q0);
                    *reinterpret_cast<uint32_t*>(C + (size_t)m * DIM + n) = pk;
                }
            }
        }
    }
}

// ============================================================================
// Fused persistent two-GEMM kernel. Phase 1: H2 = requant(X @ W1T^T), dynamic
// queue, publishes per-stripe completion. Phase 2: out = H2 @ W2T^T, dynamic
// queue in the same row-major order, spin-gated on stripe readiness. Workers
// flow from phase 1 into phase 2, filling GEMM1's tail wave with GEMM2 tiles.
// ============================================================================
__global__ void __launch_bounds__(256, 2) gemm_fused_kernel(
    const __nv_bfloat16* __restrict__ X,
    const __nv_bfloat16* __restrict__ W1T,
    const __nv_bfloat16* __restrict__ W2T,
    __nv_bfloat16* __restrict__ H2,
    float* __restrict__ Out)
{
    extern __shared__ char smem[];
    const uint32_t sbase = smem_u32(smem);
    const int tid  = threadIdx.x;
    const int wid  = tid >> 5, lane = tid & 31;
    const int wm   = (wid >> 2) * 64;   // 0 / 64
    const int wn   = (wid & 3) * 32;    // 0 / 32 / 64 / 96

    // tile-invariant addressing
    uint32_t rowbyte[4], soff[4];
    #pragma unroll
    for (int i = 0; i < 4; i++) {
        int lin = tid + i * 256;
        int row = lin >> 3, c = lin & 7;
        rowbyte[i] = (uint32_t)(row * (DIM * 2) + c * 16);
        soff[i]    = (uint32_t)(row * 128 + ((c ^ (row & 7)) << 4));
    }
    const int sw  = lane & 7;
    const int ahi = lane >> 4;
    const int bhi = (lane >> 3) & 1;
    uint32_t aRowOff[4], bRowOff[2], acol[4], bcol[4];
    #pragma unroll
    for (int mi = 0; mi < 4; mi++)
        aRowOff[mi] = (wm + mi * 16 + (lane & 7) + ((lane >> 3) & 1) * 8) * 128;
    #pragma unroll
    for (int nj = 0; nj < 2; nj++)
        bRowOff[nj] = (wn + nj * 16 + (lane & 7) + (lane >> 4) * 8) * 128;
    #pragma unroll
    for (int ks = 0; ks < 4; ks++) {
        acol[ks] = (uint32_t)(((ks * 2 + ahi) ^ sw) << 4);
        bcol[ks] = (uint32_t)(((ks * 2 + bhi) ^ sw) << 4);
    }

    __shared__ int s_next;

    // ---------------- Phase 1: H2 = requant(X @ W1T^T) ----------------
    int t = blockIdx.x;                       // grid <= NTILES
    while (t < NTILES) {
        run_tile<true>(X, W1T, H2, (t >> 5) * BM, (t & 31) * BN, sbase, lane, wm, wn,
                       rowbyte, soff, aRowOff, bRowOff, acol, bcol);
        __threadfence();                       // publish H2 stores
        __syncthreads();                       // all threads' fences done
        if (tid == 0) {
            atomicAdd(&g_sync[2 + (t >> 5)], 1);
            s_next = (int)gridDim.x + atomicAdd(&g_sync[0], 1);
        }
        __syncthreads();                       // broadcast + smem reuse barrier
        t = s_next;
    }

    // ---------------- Phase 2: Out = H2 @ W2T^T ----------------
    if (tid == 0) s_next = atomicAdd(&g_sync[1], 1);
    __syncthreads();
    t = s_next;
    while (t < NTILES) {
        if (tid == 0) {                        // wait for A-stripe of H2
            while (atomicAdd(&g_sync[2 + (t >> 5)], 0) < 32) __nanosleep(64);
        }
        __syncthreads();
        run_tile<false>(H2, W2T, Out, (t >> 5) * BM, (t & 31) * BN, sbase, lane, wm, wn,
                        rowbyte, soff, aRowOff, bRowOff, acol, bcol);
        __syncthreads();                       // reads done before next prologue
        if (tid == 0) s_next = atomicAdd(&g_sync[1], 1);
        __syncthreads();
        t = s_next;
    }
}

// ============================================================================
// Host side
// ============================================================================
extern "C" void kernel_launch(void* const* d_in, const int* in_sizes, int n_in,
                              void* d_out, int out_size) {
    const float* x_mx = (const float*)d_in[0];
    const float* mat1 = (const float*)d_in[1];
    const float* mat2 = (const float*)d_in[2];
    float* out = (float*)d_out;

    void *pX, *pW1T, *pW2T, *pH2, *pSync;
    cudaGetSymbolAddress(&pX,    g_X);
    cudaGetSymbolAddress(&pW1T,  g_W1T);
    cudaGetSymbolAddress(&pW2T,  g_W2T);
    cudaGetSymbolAddress(&pH2,   g_H2);
    cudaGetSymbolAddress(&pSync, g_sync);

    // One-time setup (outside capture; reused identically on every call).
    static cudaStream_t s1 = nullptr, s2 = nullptr, s3 = nullptr;
    static cudaEvent_t eFork = nullptr, eX = nullptr, eW1 = nullptr, eW2 = nullptr;
    static int nWorkers = 0;
    if (s1 == nullptr) {
        int prLo = 0, prHi = 0;
        cudaDeviceGetStreamPriorityRange(&prLo, &prHi);
        cudaStreamCreateWithPriority(&s1, cudaStreamNonBlocking, prHi);
        cudaStreamCreateWithPriority(&s2, cudaStreamNonBlocking, prHi);
        cudaStreamCreateWithPriority(&s3, cudaStreamNonBlocking, prHi);
        cudaEventCreateWithFlags(&eFork, cudaEventDisableTiming);
        cudaEventCreateWithFlags(&eX,    cudaEventDisableTiming);
        cudaEventCreateWithFlags(&eW1,   cudaEventDisableTiming);
        cudaEventCreateWithFlags(&eW2,   cudaEventDisableTiming);
        cudaFuncSetAttribute(gemm_fused_kernel,
                             cudaFuncAttributeMaxDynamicSharedMemorySize, SMEM_TOTAL);
        int smCount = 0;
        cudaDeviceGetAttribute(&smCount, cudaDevAttrMultiProcessorCount, 0);
        nWorkers = 2 * smCount;                      // 2 CTAs resident per SM
        if (nWorkers > NTILES) nWorkers = NTILES;
    }

    dim3 tgrid(DIM / 32, DIM / 32);

    // reset dynamic-scheduling state (graph memset node)
    cudaMemsetAsync(pSync, 0, sizeof(int) * 34, 0);

    // ---- fork: three quant kernels run concurrently on side streams ----
    cudaEventRecord(eFork, 0);
    cudaStreamWaitEvent(s1, eFork, 0);
    cudaStreamWaitEvent(s2, eFork, 0);
    cudaStreamWaitEvent(s3, eFork, 0);

    quant_rows_v4<<<(unsigned)(NELEM / 1024), 256, 0, s1>>>((const float4*)x_mx, (uint2*)pX);
    cudaEventRecord(eX, s1);
    quant_transpose_v4<<<tgrid, 256, 0, s2>>>(mat1, (__nv_bfloat16*)pW1T);
    cudaEventRecord(eW1, s2);
    quant_transpose_v4<<<tgrid, 256, 0, s3>>>(mat2, (__nv_bfloat16*)pW2T);
    cudaEventRecord(eW2, s3);

    // ---- join: fused persistent kernel needs all three quantized inputs ----
    cudaStreamWaitEvent(0, eX, 0);
    cudaStreamWaitEvent(0, eW1, 0);
    cudaStreamWaitEvent(0, eW2, 0);
    gemm_fused_kernel<<<nWorkers, 256, SMEM_TOTAL>>>(
        (const __nv_bfloat16*)pX, (const __nv_bfloat16*)pW1T,
        (const __nv_bfloat16*)pW2T, (__nv_bfloat16*)pH2, out);
}

// round 15
// speedup vs baseline: 1.3094x; 1.3094x over previous
#include <cuda_runtime.h>
#include <cuda.h>
#include <cuda_bf16.h>
#include <cuda_fp8.h>
#include <cstdint>
#include <cstddef>

// ============================================================================
// Problem constants
// ============================================================================
#define DIM 4096
#define NELEM ((size_t)DIM * (size_t)DIM)

// GEMM tiling (R5 config) with TMA loads
#define BM 128
#define BN 128
#define BK 64                        // 64 bf16 = 128 bytes per smem row (SW128)
#define NKITER (DIM / BK)            // 64
#define STAGES 3
#define TILE_BYTES (BM * BK * 2)     // 16 KB per operand tile
#define STAGE_BYTES (2 * TILE_BYTES) // 32 KB (A + B)
#define SMEM_TILES (STAGES * STAGE_BYTES)   // 96 KB
#define SMEM_ALL   (SMEM_TILES + 64)        // + barriers; 2 CTAs / SM still

// ============================================================================
// Scratch (device globals — no allocations allowed)
// ============================================================================
__device__ __align__(1024) __nv_bfloat16 g_X  [NELEM];  // quantized x       [M,K] K-major
__device__ __align__(1024) __nv_bfloat16 g_W1T[NELEM];  // quantized mat1^T  [N,K] K-major
__device__ __align__(1024) __nv_bfloat16 g_W2T[NELEM];  // quantized mat2^T  [N,K] K-major
__device__ __align__(1024) __nv_bfloat16 g_H2 [NELEM];  // requantized GEMM1 out [M,K] K-major

// ============================================================================
// Helpers
// ============================================================================
__device__ __forceinline__ uint32_t smem_u32(const void* p) {
    uint32_t a;
    asm("{ .reg .u64 t; cvta.to.shared.u64 t, %1; cvt.u32.u64 %0, t; }" : "=r"(a) : "l"(p));
    return a;
}

__device__ __forceinline__ void ldmatrix_x4(uint32_t* r, uint32_t addr) {
    asm volatile("ldmatrix.sync.aligned.m8n8.x4.shared.b16 {%0,%1,%2,%3}, [%4];"
                 : "=r"(r[0]), "=r"(r[1]), "=r"(r[2]), "=r"(r[3]) : "r"(addr));
}

__device__ __forceinline__ void mma_16816(float* c, const uint32_t* a, uint32_t b0, uint32_t b1) {
    asm volatile(
        "mma.sync.aligned.m16n8k16.row.col.f32.bf16.bf16.f32 "
        "{%0,%1,%2,%3}, {%4,%5,%6,%7}, {%8,%9}, {%0,%1,%2,%3};"
        : "+f"(c[0]), "+f"(c[1]), "+f"(c[2]), "+f"(c[3])
        : "r"(a[0]), "r"(a[1]), "r"(a[2]), "r"(a[3]), "r"(b0), "r"(b1));
}

#define MBARRIER_INIT(addr, cnt) \
    asm volatile("mbarrier.init.shared.b64 [%0], %1;" :: "r"((uint32_t)(addr)), "r"((uint32_t)(cnt)) : "memory")

#define MBARRIER_EXPECT_TX(addr, bytes) \
    asm volatile("mbarrier.arrive.expect_tx.shared.b64 _, [%0], %1;" \
                 :: "r"((uint32_t)(addr)), "r"((uint32_t)(bytes)) : "memory")

#define MBARRIER_WAIT_PARITY(mbar, parity) do {                                     \
    uint32_t _m = (uint32_t)(mbar); uint32_t _p = (uint32_t)(parity); uint32_t _d;  \
    asm volatile("{\n\t.reg .pred p;\n\t"                                           \
        "mbarrier.try_wait.parity.acquire.cta.shared::cta.b64 p, [%1], %2;\n\t"     \
        "selp.b32 %0, 1, 0, p;\n\t}" : "=r"(_d) : "r"(_m), "r"(_p) : "memory");     \
    if (!_d) {                                                                      \
        asm volatile("{\n\t.reg .pred P1;\n\t"                                      \
        "WL_%=:\n\t"                                                                \
        "mbarrier.try_wait.parity.acquire.cta.shared::cta.b64 P1, [%0], %1, 0x989680;\n\t" \
        "@P1 bra.uni WD_%=;\n\t"                                                    \
        "bra.uni WL_%=;\n\t"                                                        \
        "WD_%=:\n\t}" :: "r"(_m), "r"(_p) : "memory");                              \
    }                                                                               \
} while (0)

#define TMA_LOAD_2D(smem_addr, map_ptr, cx, cy, mbar)                                \
    asm volatile("cp.async.bulk.tensor.2d.shared::cta.global.tile.mbarrier::complete_tx::bytes " \
                 "[%0], [%1, {%2, %3}], [%4];"                                       \
                 :: "r"((uint32_t)(smem_addr)), "l"(map_ptr),                        \
                    "r"((int32_t)(cx)), "r"((int32_t)(cy)),                          \
                    "r"((uint32_t)(mbar)) : "memory")

// ============================================================================
// MX quant-dequant (exact match of the reference semantics)
// ============================================================================
__device__ __forceinline__ float mx_qd(float v, float amax) {
    if (amax == 0.0f) return 0.0f;              // all-zero block
    int e;
    frexpf(amax, &e);                           // amax = m * 2^e, m in [0.5,1)
    int se = (e - 1) - 8;                       // floor(log2(amax)) - 8 (exact)
    se = max(-127, min(127, se));
    float vs = ldexpf(v, -se);                  // v / 2^se, exact
    __nv_fp8_storage_t q = __nv_cvt_float_to_fp8(vs, __NV_SATFINITE, __NV_E4M3);
    __half_raw hr = __nv_cvt_fp8_to_halfraw(q, __NV_E4M3);
    return ldexpf(__half2float(*reinterpret_cast<__half*>(&hr)), se);
}

// ============================================================================
// Vectorized quantize along contiguous dim: 8 lanes x float4 = one 32-block.
// ============================================================================
__global__ void quant_rows_v4(const float4* __restrict__ in, uint2* __restrict__ out) {
    size_t idx = (size_t)blockIdx.x * blockDim.x + threadIdx.x;
    float4 v = in[idx];
    float a = fmaxf(fmaxf(fabsf(v.x), fabsf(v.y)), fmaxf(fabsf(v.z), fabsf(v.w)));
    #pragma unroll
    for (int off = 4; off >= 1; off >>= 1)
        a = fmaxf(a, __shfl_xor_sync(0xFFFFFFFFu, a, off, 8));
    __nv_bfloat16 q0 = __float2bfloat16(mx_qd(v.x, a));
    __nv_bfloat16 q1 = __float2bfloat16(mx_qd(v.y, a));
    __nv_bfloat16 q2 = __float2bfloat16(mx_qd(v.z, a));
    __nv_bfloat16 q3 = __float2bfloat16(mx_qd(v.w, a));
    uint2 o;
    o.x = ((uint32_t)__bfloat16_as_ushort(q1) << 16) | __bfloat16_as_ushort(q0);
    o.y = ((uint32_t)__bfloat16_as_ushort(q3) << 16) | __bfloat16_as_ushort(q2);
    out[idx] = o;
}

// Quantize mat[R, C] along last dim (C, blocks of 32), write transposed [C, R] bf16.
__global__ void quant_transpose_v4(const float* __restrict__ in, __nv_bfloat16* __restrict__ out) {
    __shared__ __nv_bfloat16 tile[32][36];   // [c][r], padded
    const int tid = threadIdx.x;
    const int r0 = blockIdx.y * 32, c0 = blockIdx.x * 32;
    {
        const int r = tid >> 3, cg = tid & 7;
        float4 v = *reinterpret_cast<const float4*>(in + (size_t)(r0 + r) * DIM + c0 + cg * 4);
        float a = fmaxf(fmaxf(fabsf(v.x), fabsf(v.y)), fmaxf(fabsf(v.z), fabsf(v.w)));
        #pragma unroll
        for (int off = 4; off >= 1; off >>= 1)
            a = fmaxf(a, __shfl_xor_sync(0xFFFFFFFFu, a, off, 8));
        tile[cg * 4 + 0][r] = __float2bfloat16(mx_qd(v.x, a));
        tile[cg * 4 + 1][r] = __float2bfloat16(mx_qd(v.y, a));
        tile[cg * 4 + 2][r] = __float2bfloat16(mx_qd(v.z, a));
        tile[cg * 4 + 3][r] = __float2bfloat16(mx_qd(v.w, a));
    }
    __syncthreads();
    {
        const int c = tid >> 3, rg = tid & 7;
        uint2 o = *reinterpret_cast<const uint2*>(&tile[c][rg * 4]);
        *reinterpret_cast<uint2*>(out + (size_t)(c0 + c) * DIM + r0 + rg * 4) = o;
    }
}

// ============================================================================
// bf16 HMMA GEMM with TMA loads: C[m,n] = sum_k A[m,k] * B[n,k]
//   CTA tile 128x128x64, 256 threads = 8 warps (2m x 4n), warp tile 64x32.
//   3-stage TMA + mbarrier pipeline. ALL smem (tiles + barriers) lives in the
//   dynamic window so stage bases stay 1024-aligned (TMA SW128 requirement —
//   the R13 static/dynamic mix broke this). 2 CTAs / SM.
// ============================================================================
template <bool REQUANT>
__global__ void __launch_bounds__(256, 2) gemm_bf16_kernel(
    const __grid_constant__ CUtensorMap tmA,
    const __grid_constant__ CUtensorMap tmB,
    void* __restrict__ Cout)
{
    extern __shared__ char smem[];
    const uint32_t sbase = smem_u32(smem);           // dynamic window base (1024-aligned)
    const uint32_t bar0  = sbase + SMEM_TILES;       // barriers after the 3 stages
    const int tid  = threadIdx.x;
    const int wid  = tid >> 5, lane = tid & 31;
    const int m0   = blockIdx.y * BM, n0 = blockIdx.x * BN;
    const int wm   = (wid >> 2) * 64;   // 0 / 64
    const int wn   = (wid & 3) * 32;    // 0 / 32 / 64 / 96

    if (tid == 0) {
        #pragma unroll
        for (int s = 0; s < STAGES; s++) MBARRIER_INIT(bar0 + s * 8, 1);
    }
    __syncthreads();

    // ---- per-lane ldmatrix addressing (identical to R5) ----
    const int sw  = lane & 7;
    const int ahi = lane >> 4;
    const int bhi = (lane >> 3) & 1;
    uint32_t aRowOff[4], bRowOff[2], acol[4], bcol[4];
    #pragma unroll
    for (int mi = 0; mi < 4; mi++)
        aRowOff[mi] = (wm + mi * 16 + (lane & 7) + ((lane >> 3) & 1) * 8) * 128;
    #pragma unroll
    for (int nj = 0; nj < 2; nj++)
        bRowOff[nj] = (wn + nj * 16 + (lane & 7) + (lane >> 4) * 8) * 128;
    #pragma unroll
    for (int ks = 0; ks < 4; ks++) {
        acol[ks] = (uint32_t)(((ks * 2 + ahi) ^ sw) << 4);
        bcol[ks] = (uint32_t)(((ks * 2 + bhi) ^ sw) << 4);
    }

    float acc[4][4][4];
    #pragma unroll
    for (int mi = 0; mi < 4; mi++)
        #pragma unroll
        for (int ni = 0; ni < 4; ni++)
            #pragma unroll
            for (int j = 0; j < 4; j++) acc[mi][ni][j] = 0.0f;

    // ---- prologue: TMA-load stages 0 and 1 ----
    if (tid == 0) {
        #pragma unroll
        for (int s = 0; s < 2; s++) {
            const uint32_t sA = sbase + s * STAGE_BYTES;
            MBARRIER_EXPECT_TX(bar0 + s * 8, 2 * TILE_BYTES);
            TMA_LOAD_2D(sA, &tmA, s * BK, m0, bar0 + s * 8);
            TMA_LOAD_2D(sA + TILE_BYTES, &tmB, s * BK, n0, bar0 + s * 8);
        }
    }

    int slotC = 0, slotP = 2;

    for (int kt = 0; kt < NKITER; kt++) {
        const uint32_t ph = (uint32_t)((kt / STAGES) & 1);   // parity of slotC's use
        MBARRIER_WAIT_PARITY(bar0 + slotC * 8, ph);          // tile kt resident
        __syncthreads();                                      // slotP-old reads done

        if (kt + 2 < NKITER && tid == 0) {
            const uint32_t sA = sbase + (uint32_t)slotP * STAGE_BYTES;
            MBARRIER_EXPECT_TX(bar0 + slotP * 8, 2 * TILE_BYTES);
            TMA_LOAD_2D(sA, &tmA, (kt + 2) * BK, m0, bar0 + slotP * 8);
            TMA_LOAD_2D(sA + TILE_BYTES, &tmB, (kt + 2) * BK, n0, bar0 + slotP * 8);
        }

        const uint32_t sA = sbase + (uint32_t)slotC * STAGE_BYTES;
        const uint32_t sB = sA + TILE_BYTES;

        #pragma unroll
        for (int ks = 0; ks < BK / 16; ks++) {
            uint32_t afr[4][4], bfr[2][4];
            #pragma unroll
            for (int mi = 0; mi < 4; mi++) ldmatrix_x4(afr[mi], sA + aRowOff[mi] + acol[ks]);
            #pragma unroll
            for (int nj = 0; nj < 2; nj++) ldmatrix_x4(bfr[nj], sB + bRowOff[nj] + bcol[ks]);
            #pragma unroll
            for (int mi = 0; mi < 4; mi++)
                #pragma unroll
                for (int ni = 0; ni < 4; ni++)
                    mma_16816(acc[mi][ni], afr[mi],
                              bfr[ni >> 1][(ni & 1) * 2], bfr[ni >> 1][(ni & 1) * 2 + 1]);
        }

        slotC = (slotC == STAGES - 1) ? 0 : slotC + 1;
        slotP = (slotP == STAGES - 1) ? 0 : slotP + 1;
    }

    // ---- epilogue (identical to R5) ----
    const int tr = lane >> 2, tc = (lane & 3) * 2;
    if (!REQUANT) {
        float* C = (float*)Cout;
        #pragma unroll
        for (int mi = 0; mi < 4; mi++) {
            const int m = m0 + wm + mi * 16 + tr;
            #pragma unroll
            for (int ni = 0; ni < 4; ni++) {
                const int n = n0 + wn + ni * 8 + tc;
                *reinterpret_cast<float2*>(C + (size_t)m * DIM + n) =
                    make_float2(acc[mi][ni][0], acc[mi][ni][1]);
                *reinterpret_cast<float2*>(C + (size_t)(m + 8) * DIM + n) =
                    make_float2(acc[mi][ni][2], acc[mi][ni][3]);
            }
        }
    } else {
        // Warp's N-range [n0+wn, n0+wn+32) is exactly one MX block per row.
        __nv_bfloat16* C = (__nv_bfloat16*)Cout;
        #pragma unroll
        for (int mi = 0; mi < 4; mi++) {
            #pragma unroll
            for (int h = 0; h < 2; h++) {          // row tr  /  row tr+8
                float a = 0.0f;
                #pragma unroll
                for (int ni = 0; ni < 4; ni++)
                    a = fmaxf(a, fmaxf(fabsf(acc[mi][ni][2 * h]),
                                       fabsf(acc[mi][ni][2 * h + 1])));
                a = fmaxf(a, __shfl_xor_sync(0xFFFFFFFFu, a, 1, 4));
                a = fmaxf(a, __shfl_xor_sync(0xFFFFFFFFu, a, 2, 4));
                const int m = m0 + wm + mi * 16 + h * 8 + tr;
                #pragma unroll
                for (int ni = 0; ni < 4; ni++) {
                    const int n = n0 + wn + ni * 8 + tc;
                    __nv_bfloat16 q0 = __float2bfloat16(mx_qd(acc[mi][ni][2 * h], a));
                    __nv_bfloat16 q1 = __float2bfloat16(mx_qd(acc[mi][ni][2 * h + 1], a));
                    uint32_t pk = ((uint32_t)__bfloat16_as_ushort(q1) << 16) |
                                  __bfloat16_as_ushort(q0);
                    *reinterpret_cast<uint32_t*>(C + (size_t)m * DIM + n) = pk;
                }
            }
        }
    }
}

// ============================================================================
// Host side
// ============================================================================
typedef CUresult (CUDAAPI* PFN_tmEncode_t)(
    CUtensorMap*, CUtensorMapDataType, cuuint32_t, void*,
    const cuuint64_t*, const cuuint64_t*, const cuuint32_t*, const cuuint32_t*,
    CUtensorMapInterleave, CUtensorMapSwizzle, CUtensorMapL2promotion,
    CUtensorMapFloatOOBfill);

static void make_bf16_map(PFN_tmEncode_t fn, CUtensorMap* tm, void* ptr) {
    cuuint64_t dims[2]    = {DIM, DIM};                       // dim0 = K (contiguous)
    cuuint64_t strides[1] = {DIM * sizeof(__nv_bfloat16)};    // row pitch (bytes)
    cuuint32_t box[2]     = {BK, BM};                         // 128B x 128 rows (SW128)
    cuuint32_t estr[2]    = {1, 1};
    fn(tm, CU_TENSOR_MAP_DATA_TYPE_BFLOAT16, 2, ptr, dims, strides, box, estr,
       CU_TENSOR_MAP_INTERLEAVE_NONE, CU_TENSOR_MAP_SWIZZLE_128B,
       CU_TENSOR_MAP_L2_PROMOTION_L2_128B, CU_TENSOR_MAP_FLOAT_OOB_FILL_NONE);
}

extern "C" void kernel_launch(void* const* d_in, const int* in_sizes, int n_in,
                              void* d_out, int out_size) {
    const float* x_mx = (const float*)d_in[0];
    const float* mat1 = (const float*)d_in[1];
    const float* mat2 = (const float*)d_in[2];
    float* out = (float*)d_out;

    void *pX, *pW1T, *pW2T, *pH2;
    cudaGetSymbolAddress(&pX,   g_X);
    cudaGetSymbolAddress(&pW1T, g_W1T);
    cudaGetSymbolAddress(&pW2T, g_W2T);
    cudaGetSymbolAddress(&pH2,  g_H2);

    // One-time setup (outside capture; reused identically on every call).
    static cudaStream_t s1 = nullptr, s2 = nullptr, s3 = nullptr;
    static cudaEvent_t eFork = nullptr, eX = nullptr, eW1 = nullptr, eW2 = nullptr;
    static CUtensorMap tmX, tmW1T, tmW2T, tmH2;
    if (s1 == nullptr) {
        cudaStreamCreateWithFlags(&s1, cudaStreamNonBlocking);
        cudaStreamCreateWithFlags(&s2, cudaStreamNonBlocking);
        cudaStreamCreateWithFlags(&s3, cudaStreamNonBlocking);
        cudaEventCreateWithFlags(&eFork, cudaEventDisableTiming);
        cudaEventCreateWithFlags(&eX,    cudaEventDisableTiming);
        cudaEventCreateWithFlags(&eW1,   cudaEventDisableTiming);
        cudaEventCreateWithFlags(&eW2,   cudaEventDisableTiming);
        cudaFuncSetAttribute(gemm_bf16_kernel<false>,
                             cudaFuncAttributeMaxDynamicSharedMemorySize, SMEM_ALL);
        cudaFuncSetAttribute(gemm_bf16_kernel<true>,
                             cudaFuncAttributeMaxDynamicSharedMemorySize, SMEM_ALL);
        PFN_tmEncode_t tmEncode = nullptr;
        cudaDriverEntryPointQueryResult qres;
        cudaGetDriverEntryPointByVersion("cuTensorMapEncodeTiled", (void**)&tmEncode,
                                         12000, cudaEnableDefault, &qres);
        make_bf16_map(tmEncode, &tmX,   pX);
        make_bf16_map(tmEncode, &tmW1T, pW1T);
        make_bf16_map(tmEncode, &tmW2T, pW2T);
        make_bf16_map(tmEncode, &tmH2,  pH2);
    }

    dim3 tgrid(DIM / 32, DIM / 32);
    dim3 ggrid(DIM / BN, DIM / BM);

    // ---- fork: three quant kernels run concurrently on side streams ----
    cudaEventRecord(eFork, 0);
    cudaStreamWaitEvent(s1, eFork, 0);
    cudaStreamWaitEvent(s2, eFork, 0);
    cudaStreamWaitEvent(s3, eFork, 0);

    quant_rows_v4<<<(unsigned)(NELEM / 1024), 256, 0, s1>>>((const float4*)x_mx, (uint2*)pX);
    cudaEventRecord(eX, s1);
    quant_transpose_v4<<<tgrid, 256, 0, s2>>>(mat1, (__nv_bfloat16*)pW1T);
    cudaEventRecord(eW1, s2);
    quant_transpose_v4<<<tgrid, 256, 0, s3>>>(mat2, (__nv_bfloat16*)pW2T);
    cudaEventRecord(eW2, s3);

    // ---- GEMM1 needs X + W1T; W2T quant overlaps it on s3 ----
    cudaStreamWaitEvent(0, eX, 0);
    cudaStreamWaitEvent(0, eW1, 0);
    gemm_bf16_kernel<true><<<ggrid, 256, SMEM_ALL>>>(tmX, tmW1T, pH2);

    // ---- GEMM2 additionally needs W2T ----
    cudaStreamWaitEvent(0, eW2, 0);
    gemm_bf16_kernel<false><<<ggrid, 256, SMEM_ALL>>>(tmH2, tmW2T, out);
}

// round 16
// speedup vs baseline: 1.3855x; 1.0582x over previous
#include <cuda_runtime.h>
#include <cuda.h>
#include <cuda_bf16.h>
#include <cuda_fp8.h>
#include <cstdint>
#include <cstddef>

// ============================================================================
// Problem constants
// ============================================================================
#define DIM 4096
#define NELEM ((size_t)DIM * (size_t)DIM)

// GEMM tiling (R5 config) with TMA loads
#define BM 128
#define BN 128
#define BK 64                        // 64 bf16 = 128 bytes per smem row (SW128)
#define NKITER (DIM / BK)            // 64
#define STAGES 3
#define TILE_BYTES (BM * BK * 2)     // 16 KB per operand tile
#define STAGE_BYTES (2 * TILE_BYTES) // 32 KB (A + B)
#define SMEM_TILES (STAGES * STAGE_BYTES)   // 96 KB
#define SMEM_ALL   (SMEM_TILES + 64)        // + barriers; 2 CTAs / SM still

// ============================================================================
// Scratch (device globals — no allocations allowed)
// ============================================================================
__device__ __align__(1024) __nv_bfloat16 g_X  [NELEM];  // quantized x       [M,K] K-major
__device__ __align__(1024) __nv_bfloat16 g_W1T[NELEM];  // quantized mat1^T  [N,K] K-major
__device__ __align__(1024) __nv_bfloat16 g_W2T[NELEM];  // quantized mat2^T  [N,K] K-major
__device__ __align__(1024) __nv_bfloat16 g_H2 [NELEM];  // requantized GEMM1 out [M,K] K-major

// ============================================================================
// Helpers
// ============================================================================
__device__ __forceinline__ uint32_t smem_u32(const void* p) {
    uint32_t a;
    asm("{ .reg .u64 t; cvta.to.shared.u64 t, %1; cvt.u32.u64 %0, t; }" : "=r"(a) : "l"(p));
    return a;
}

__device__ __forceinline__ void ldmatrix_x4(uint32_t* r, uint32_t addr) {
    asm volatile("ldmatrix.sync.aligned.m8n8.x4.shared.b16 {%0,%1,%2,%3}, [%4];"
                 : "=r"(r[0]), "=r"(r[1]), "=r"(r[2]), "=r"(r[3]) : "r"(addr));
}

__device__ __forceinline__ void mma_16816(float* c, const uint32_t* a, uint32_t b0, uint32_t b1) {
    asm volatile(
        "mma.sync.aligned.m16n8k16.row.col.f32.bf16.bf16.f32 "
        "{%0,%1,%2,%3}, {%4,%5,%6,%7}, {%8,%9}, {%0,%1,%2,%3};"
        : "+f"(c[0]), "+f"(c[1]), "+f"(c[2]), "+f"(c[3])
        : "r"(a[0]), "r"(a[1]), "r"(a[2]), "r"(a[3]), "r"(b0), "r"(b1));
}

#define MBARRIER_INIT(addr, cnt) \
    asm volatile("mbarrier.init.shared.b64 [%0], %1;" :: "r"((uint32_t)(addr)), "r"((uint32_t)(cnt)) : "memory")

#define MBARRIER_EXPECT_TX(addr, bytes) \
    asm volatile("mbarrier.arrive.expect_tx.shared.b64 _, [%0], %1;" \
                 :: "r"((uint32_t)(addr)), "r"((uint32_t)(bytes)) : "memory")

#define MBARRIER_WAIT_PARITY(mbar, parity) do {                                     \
    uint32_t _m = (uint32_t)(mbar); uint32_t _p = (uint32_t)(parity); uint32_t _d;  \
    asm volatile("{\n\t.reg .pred p;\n\t"                                           \
        "mbarrier.try_wait.parity.acquire.cta.shared::cta.b64 p, [%1], %2;\n\t"     \
        "selp.b32 %0, 1, 0, p;\n\t}" : "=r"(_d) : "r"(_m), "r"(_p) : "memory");     \
    if (!_d) {                                                                      \
        asm volatile("{\n\t.reg .pred P1;\n\t"                                      \
        "WL_%=:\n\t"                                                                \
        "mbarrier.try_wait.parity.acquire.cta.shared::cta.b64 P1, [%0], %1, 0x989680;\n\t" \
        "@P1 bra.uni WD_%=;\n\t"                                                    \
        "bra.uni WL_%=;\n\t"                                                        \
        "WD_%=:\n\t}" :: "r"(_m), "r"(_p) : "memory");                              \
    }                                                                               \
} while (0)

#define TMA_LOAD_2D(smem_addr, map_ptr, cx, cy, mbar)                                \
    asm volatile("cp.async.bulk.tensor.2d.shared::cta.global.tile.mbarrier::complete_tx::bytes " \
                 "[%0], [%1, {%2, %3}], [%4];"                                       \
                 :: "r"((uint32_t)(smem_addr)), "l"(map_ptr),                        \
                    "r"((int32_t)(cx)), "r"((int32_t)(cy)),                          \
                    "r"((uint32_t)(mbar)) : "memory")

// ============================================================================
// MX quant-dequant — bit-exact fast path (no frexpf/ldexpf).
// For any amax reachable here (max |.| over 32 normal-range fp32 values or
// fp32 dot products; subnormals unreachable), floor(log2(amax)) equals the
// unbiased exponent field, and 2^±se are exact power-of-two floats built
// directly from bits. Power-of-two multiply == reference's exact division.
// ============================================================================
__device__ __forceinline__ float mx_qd(float v, float amax) {
    if (amax == 0.0f) return 0.0f;                       // all-zero block
    int e  = (int)(__float_as_uint(amax) >> 23) - 127;   // floor(log2(amax))
    int se = e - 8;                                      // shared exponent
    se = max(-127, min(127, se));
    const float rscale = __uint_as_float((uint32_t)(127 - se) << 23);  // 2^-se
    const float scale  = __uint_as_float((uint32_t)(127 + se) << 23);  // 2^se
    __nv_fp8_storage_t q = __nv_cvt_float_to_fp8(v * rscale, __NV_SATFINITE, __NV_E4M3);
    __half_raw hr = __nv_cvt_fp8_to_halfraw(q, __NV_E4M3);
    return __half2float(*reinterpret_cast<__half*>(&hr)) * scale;
}

// ============================================================================
// Vectorized quantize along contiguous dim: 8 lanes x float4 = one 32-block.
// ============================================================================
__global__ void quant_rows_v4(const float4* __restrict__ in, uint2* __restrict__ out) {
    size_t idx = (size_t)blockIdx.x * blockDim.x + threadIdx.x;
    float4 v = in[idx];
    float a = fmaxf(fmaxf(fabsf(v.x), fabsf(v.y)), fmaxf(fabsf(v.z), fabsf(v.w)));
    #pragma unroll
    for (int off = 4; off >= 1; off >>= 1)
        a = fmaxf(a, __shfl_xor_sync(0xFFFFFFFFu, a, off, 8));
    __nv_bfloat16 q0 = __float2bfloat16(mx_qd(v.x, a));
    __nv_bfloat16 q1 = __float2bfloat16(mx_qd(v.y, a));
    __nv_bfloat16 q2 = __float2bfloat16(mx_qd(v.z, a));
    __nv_bfloat16 q3 = __float2bfloat16(mx_qd(v.w, a));
    uint2 o;
    o.x = ((uint32_t)__bfloat16_as_ushort(q1) << 16) | __bfloat16_as_ushort(q0);
    o.y = ((uint32_t)__bfloat16_as_ushort(q3) << 16) | __bfloat16_as_ushort(q2);
    out[idx] = o;
}

// Quantize mat[R, C] along last dim (C, blocks of 32), write transposed [C, R] bf16.
__global__ void quant_transpose_v4(const float* __restrict__ in, __nv_bfloat16* __restrict__ out) {
    __shared__ __nv_bfloat16 tile[32][36];   // [c][r], padded
    const int tid = threadIdx.x;
    const int r0 = blockIdx.y * 32, c0 = blockIdx.x * 32;
    {
        const int r = tid >> 3, cg = tid & 7;
        float4 v = *reinterpret_cast<const float4*>(in + (size_t)(r0 + r) * DIM + c0 + cg * 4);
        float a = fmaxf(fmaxf(fabsf(v.x), fabsf(v.y)), fmaxf(fabsf(v.z), fabsf(v.w)));
        #pragma unroll
        for (int off = 4; off >= 1; off >>= 1)
            a = fmaxf(a, __shfl_xor_sync(0xFFFFFFFFu, a, off, 8));
        tile[cg * 4 + 0][r] = __float2bfloat16(mx_qd(v.x, a));
        tile[cg * 4 + 1][r] = __float2bfloat16(mx_qd(v.y, a));
        tile[cg * 4 + 2][r] = __float2bfloat16(mx_qd(v.z, a));
        tile[cg * 4 + 3][r] = __float2bfloat16(mx_qd(v.w, a));
    }
    __syncthreads();
    {
        const int c = tid >> 3, rg = tid & 7;
        uint2 o = *reinterpret_cast<const uint2*>(&tile[c][rg * 4]);
        *reinterpret_cast<uint2*>(out + (size_t)(c0 + c) * DIM + r0 + rg * 4) = o;
    }
}

// ============================================================================
// bf16 HMMA GEMM with TMA loads: C[m,n] = sum_k A[m,k] * B[n,k]
//   CTA tile 128x128x64, 256 threads = 8 warps (2m x 4n), warp tile 64x32.
//   3-stage TMA + mbarrier pipeline; all smem in the dynamic window
//   (stage bases 1024-aligned for SW128). 2 CTAs / SM.
// ============================================================================
template <bool REQUANT>
__global__ void __launch_bounds__(256, 2) gemm_bf16_kernel(
    const __grid_constant__ CUtensorMap tmA,
    const __grid_constant__ CUtensorMap tmB,
    void* __restrict__ Cout)
{
    extern __shared__ char smem[];
    const uint32_t sbase = smem_u32(smem);           // dynamic window base (1024-aligned)
    const uint32_t bar0  = sbase + SMEM_TILES;       // barriers after the 3 stages
    const int tid  = threadIdx.x;
    const int wid  = tid >> 5, lane = tid & 31;
    const int m0   = blockIdx.y * BM, n0 = blockIdx.x * BN;
    const int wm   = (wid >> 2) * 64;   // 0 / 64
    const int wn   = (wid & 3) * 32;    // 0 / 32 / 64 / 96

    if (tid == 0) {
        #pragma unroll
        for (int s = 0; s < STAGES; s++) MBARRIER_INIT(bar0 + s * 8, 1);
    }
    __syncthreads();

    // ---- per-lane ldmatrix addressing ----
    const int sw  = lane & 7;
    const int ahi = lane >> 4;
    const int bhi = (lane >> 3) & 1;
    uint32_t aRowOff[4], bRowOff[2], acol[4], bcol[4];
    #pragma unroll
    for (int mi = 0; mi < 4; mi++)
        aRowOff[mi] = (wm + mi * 16 + (lane & 7) + ((lane >> 3) & 1) * 8) * 128;
    #pragma unroll
    for (int nj = 0; nj < 2; nj++)
        bRowOff[nj] = (wn + nj * 16 + (lane & 7) + (lane >> 4) * 8) * 128;
    #pragma unroll
    for (int ks = 0; ks < 4; ks++) {
        acol[ks] = (uint32_t)(((ks * 2 + ahi) ^ sw) << 4);
        bcol[ks] = (uint32_t)(((ks * 2 + bhi) ^ sw) << 4);
    }

    float acc[4][4][4];
    #pragma unroll
    for (int mi = 0; mi < 4; mi++)
        #pragma unroll
        for (int ni = 0; ni < 4; ni++)
            #pragma unroll
            for (int j = 0; j < 4; j++) acc[mi][ni][j] = 0.0f;

    // ---- prologue: TMA-load stages 0 and 1 ----
    if (tid == 0) {
        #pragma unroll
        for (int s = 0; s < 2; s++) {
            const uint32_t sA = sbase + s * STAGE_BYTES;
            MBARRIER_EXPECT_TX(bar0 + s * 8, 2 * TILE_BYTES);
            TMA_LOAD_2D(sA, &tmA, s * BK, m0, bar0 + s * 8);
            TMA_LOAD_2D(sA + TILE_BYTES, &tmB, s * BK, n0, bar0 + s * 8);
        }
    }

    int slotC = 0, slotP = 2;

    for (int kt = 0; kt < NKITER; kt++) {
        const uint32_t ph = (uint32_t)((kt / STAGES) & 1);   // parity of slotC's use
        MBARRIER_WAIT_PARITY(bar0 + slotC * 8, ph);          // tile kt resident
        __syncthreads();                                      // slotP-old reads done

        if (kt + 2 < NKITER && tid == 0) {
            const uint32_t sA = sbase + (uint32_t)slotP * STAGE_BYTES;
            MBARRIER_EXPECT_TX(bar0 + slotP * 8, 2 * TILE_BYTES);
            TMA_LOAD_2D(sA, &tmA, (kt + 2) * BK, m0, bar0 + slotP * 8);
            TMA_LOAD_2D(sA + TILE_BYTES, &tmB, (kt + 2) * BK, n0, bar0 + slotP * 8);
        }

        const uint32_t sA = sbase + (uint32_t)slotC * STAGE_BYTES;
        const uint32_t sB = sA + TILE_BYTES;

        #pragma unroll
        for (int ks = 0; ks < BK / 16; ks++) {
            uint32_t afr[4][4], bfr[2][4];
            #pragma unroll
            for (int mi = 0; mi < 4; mi++) ldmatrix_x4(afr[mi], sA + aRowOff[mi] + acol[ks]);
            #pragma unroll
            for (int nj = 0; nj < 2; nj++) ldmatrix_x4(bfr[nj], sB + bRowOff[nj] + bcol[ks]);
            #pragma unroll
            for (int mi = 0; mi < 4; mi++)
                #pragma unroll
                for (int ni = 0; ni < 4; ni++)
                    mma_16816(acc[mi][ni], afr[mi],
                              bfr[ni >> 1][(ni & 1) * 2], bfr[ni >> 1][(ni & 1) * 2 + 1]);
        }

        slotC = (slotC == STAGES - 1) ? 0 : slotC + 1;
        slotP = (slotP == STAGES - 1) ? 0 : slotP + 1;
    }

    // ---- epilogue ----
    const int tr = lane >> 2, tc = (lane & 3) * 2;
    if (!REQUANT) {
        float* C = (float*)Cout;
        #pragma unroll
        for (int mi = 0; mi < 4; mi++) {
            const int m = m0 + wm + mi * 16 + tr;
            #pragma unroll
            for (int ni = 0; ni < 4; ni++) {
                const int n = n0 + wn + ni * 8 + tc;
                *reinterpret_cast<float2*>(C + (size_t)m * DIM + n) =
                    make_float2(acc[mi][ni][0], acc[mi][ni][1]);
                *reinterpret_cast<float2*>(C + (size_t)(m + 8) * DIM + n) =
                    make_float2(acc[mi][ni][2], acc[mi][ni][3]);
            }
        }
    } else {
        // Warp's N-range [n0+wn, n0+wn+32) is exactly one MX block per row.
        __nv_bfloat16* C = (__nv_bfloat16*)Cout;
        #pragma unroll
        for (int mi = 0; mi < 4; mi++) {
            #pragma unroll
            for (int h = 0; h < 2; h++) {          // row tr  /  row tr+8
                float a = 0.0f;
                #pragma unroll
                for (int ni = 0; ni < 4; ni++)
                    a = fmaxf(a, fmaxf(fabsf(acc[mi][ni][2 * h]),
                                       fabsf(acc[mi][ni][2 * h + 1])));
                a = fmaxf(a, __shfl_xor_sync(0xFFFFFFFFu, a, 1, 4));
                a = fmaxf(a, __shfl_xor_sync(0xFFFFFFFFu, a, 2, 4));
                const int m = m0 + wm + mi * 16 + h * 8 + tr;
                #pragma unroll
                for (int ni = 0; ni < 4; ni++) {
                    const int n = n0 + wn + ni * 8 + tc;
                    __nv_bfloat16 q0 = __float2bfloat16(mx_qd(acc[mi][ni][2 * h], a));
                    __nv_bfloat16 q1 = __float2bfloat16(mx_qd(acc[mi][ni][2 * h + 1], a));
                    uint32_t pk = ((uint32_t)__bfloat16_as_ushort(q1) << 16) |
                                  __bfloat16_as_ushort(q0);
                    *reinterpret_cast<uint32_t*>(C + (size_t)m * DIM + n) = pk;
                }
            }
        }
    }
}

// ============================================================================
// Host side
// ============================================================================
typedef CUresult (CUDAAPI* PFN_tmEncode_t)(
    CUtensorMap*, CUtensorMapDataType, cuuint32_t, void*,
    const cuuint64_t*, const cuuint64_t*, const cuuint32_t*, const cuuint32_t*,
    CUtensorMapInterleave, CUtensorMapSwizzle, CUtensorMapL2promotion,
    CUtensorMapFloatOOBfill);

static void make_bf16_map(PFN_tmEncode_t fn, CUtensorMap* tm, void* ptr) {
    cuuint64_t dims[2]    = {DIM, DIM};                       // dim0 = K (contiguous)
    cuuint64_t strides[1] = {DIM * sizeof(__nv_bfloat16)};    // row pitch (bytes)
    cuuint32_t box[2]     = {BK, BM};                         // 128B x 128 rows (SW128)
    cuuint32_t estr[2]    = {1, 1};
    fn(tm, CU_TENSOR_MAP_DATA_TYPE_BFLOAT16, 2, ptr, dims, strides, box, estr,
       CU_TENSOR_MAP_INTERLEAVE_NONE, CU_TENSOR_MAP_SWIZZLE_128B,
       CU_TENSOR_MAP_L2_PROMOTION_L2_128B, CU_TENSOR_MAP_FLOAT_OOB_FILL_NONE);
}

extern "C" void kernel_launch(void* const* d_in, const int* in_sizes, int n_in,
                              void* d_out, int out_size) {
    const float* x_mx = (const float*)d_in[0];
    const float* mat1 = (const float*)d_in[1];
    const float* mat2 = (const float*)d_in[2];
    float* out = (float*)d_out;

    void *pX, *pW1T, *pW2T, *pH2;
    cudaGetSymbolAddress(&pX,   g_X);
    cudaGetSymbolAddress(&pW1T, g_W1T);
    cudaGetSymbolAddress(&pW2T, g_W2T);
    cudaGetSymbolAddress(&pH2,  g_H2);

    // One-time setup (outside capture; reused identically on every call).
    static cudaStream_t s1 = nullptr, s2 = nullptr, s3 = nullptr;
    static cudaEvent_t eFork = nullptr, eX = nullptr, eW1 = nullptr, eW2 = nullptr;
    static CUtensorMap tmX, tmW1T, tmW2T, tmH2;
    if (s1 == nullptr) {
        cudaStreamCreateWithFlags(&s1, cudaStreamNonBlocking);
        cudaStreamCreateWithFlags(&s2, cudaStreamNonBlocking);
        cudaStreamCreateWithFlags(&s3, cudaStreamNonBlocking);
        cudaEventCreateWithFlags(&eFork, cudaEventDisableTiming);
        cudaEventCreateWithFlags(&eX,    cudaEventDisableTiming);
        cudaEventCreateWithFlags(&eW1,   cudaEventDisableTiming);
        cudaEventCreateWithFlags(&eW2,   cudaEventDisableTiming);
        cudaFuncSetAttribute(gemm_bf16_kernel<false>,
                             cudaFuncAttributeMaxDynamicSharedMemorySize, SMEM_ALL);
        cudaFuncSetAttribute(gemm_bf16_kernel<true>,
                             cudaFuncAttributeMaxDynamicSharedMemorySize, SMEM_ALL);
        PFN_tmEncode_t tmEncode = nullptr;
        cudaDriverEntryPointQueryResult qres;
        cudaGetDriverEntryPointByVersion("cuTensorMapEncodeTiled", (void**)&tmEncode,
                                         12000, cudaEnableDefault, &qres);
        make_bf16_map(tmEncode, &tmX,   pX);
        make_bf16_map(tmEncode, &tmW1T, pW1T);
        make_bf16_map(tmEncode, &tmW2T, pW2T);
        make_bf16_map(tmEncode, &tmH2,  pH2);
    }

    dim3 tgrid(DIM / 32, DIM / 32);
    dim3 ggrid(DIM / BN, DIM / BM);

    // ---- fork: three quant kernels run concurrently on side streams ----
    cudaEventRecord(eFork, 0);
    cudaStreamWaitEvent(s1, eFork, 0);
    cudaStreamWaitEvent(s2, eFork, 0);
    cudaStreamWaitEvent(s3, eFork, 0);

    quant_rows_v4<<<(unsigned)(NELEM / 1024), 256, 0, s1>>>((const float4*)x_mx, (uint2*)pX);
    cudaEventRecord(eX, s1);
    quant_transpose_v4<<<tgrid, 256, 0, s2>>>(mat1, (__nv_bfloat16*)pW1T);
    cudaEventRecord(eW1, s2);
    quant_transpose_v4<<<tgrid, 256, 0, s3>>>(mat2, (__nv_bfloat16*)pW2T);
    cudaEventRecord(eW2, s3);

    // ---- GEMM1 needs X + W1T; W2T quant overlaps it on s3 ----
    cudaStreamWaitEvent(0, eX, 0);
    cudaStreamWaitEvent(0, eW1, 0);
    gemm_bf16_kernel<true><<<ggrid, 256, SMEM_ALL>>>(tmX, tmW1T, pH2);

    // ---- GEMM2 additionally needs W2T ----
    cudaStreamWaitEvent(0, eW2, 0);
    gemm_bf16_kernel<false><<<ggrid, 256, SMEM_ALL>>>(tmH2, tmW2T, out);
}